// round 9
// baseline (speedup 1.0000x reference)
#include <cuda_runtime.h>
#include <cuda_bf16.h>
#include <cstdint>

#define N_POS 65536   // 16*64*64

// Scratch (allocation-free rule: __device__ globals)
__device__ float g_q[64 * N_POS];
__device__ float g_k[64 * N_POS];
__device__ float g_v[64 * N_POS];

// ---------------------------------------------------------------------------
// Helpers (arch-agnostic PTX only: mma.sync + ldmatrix, sm_80+)
// ---------------------------------------------------------------------------
__device__ __forceinline__ uint32_t smem_u32(const void* p) {
    return (uint32_t)__cvta_generic_to_shared(p);
}

__device__ __forceinline__ void mma_bf16(float* c, const uint32_t* a, uint32_t b0, uint32_t b1) {
    asm volatile(
        "mma.sync.aligned.m16n8k16.row.col.f32.bf16.bf16.f32 "
        "{%0,%1,%2,%3}, {%4,%5,%6,%7}, {%8,%9}, {%0,%1,%2,%3};"
        : "+f"(c[0]), "+f"(c[1]), "+f"(c[2]), "+f"(c[3])
        : "r"(a[0]), "r"(a[1]), "r"(a[2]), "r"(a[3]), "r"(b0), "r"(b1));
}

#define LDSM_X4(r0, r1, r2, r3, addr)                                          \
    asm volatile("ldmatrix.sync.aligned.m8n8.x4.shared.b16 {%0,%1,%2,%3}, [%4];" \
                 : "=r"(r0), "=r"(r1), "=r"(r2), "=r"(r3) : "r"(addr))

__device__ __forceinline__ void bf16split(float x, uint16_t& h, uint16_t& l) {
    __nv_bfloat16 hb = __float2bfloat16(x);
    __nv_bfloat16 lb = __float2bfloat16(x - __bfloat162float(hb));
    h = __bfloat16_as_ushort(hb);
    l = __bfloat16_as_ushort(lb);
}
__device__ __forceinline__ uint32_t pck(uint16_t lo, uint16_t hi) {
    return (uint32_t)lo | ((uint32_t)hi << 16);
}

// ---------------------------------------------------------------------------
// Kernel A: q/k/v 1x1 conv as bf16 HMMA GEMM with 2-term split
// (hi*hi + hi*lo + lo*hi, fp32 accumulate -> ~1e-5 rel err).
// 256 threads / 8 warps, 2 CTAs per SM (phase overlap across CTAs).
// CTA = 128 positions.  24 warp-subtiles = {q,k,v} x 4 row-groups x 2
// position-halves; each warp walks 3 subtiles sequentially (acc = 32 regs).
// ---------------------------------------------------------------------------
#define PTILE 128
#define CSTR 36   // uint32 stride per position column (36*4 = 144 B)

__global__ __launch_bounds__(256, 2) void qkv_mma_kernel(
    const float* __restrict__ x,
    const float* __restrict__ wq,
    const float* __restrict__ wk,
    const float* __restrict__ wv)
{
    __shared__ uint32_t sXhi[PTILE * CSTR];   // 18432 B
    __shared__ uint32_t sXlo[PTILE * CSTR];   // 18432 B

    const int tid  = threadIdx.x;
    const int wid  = tid >> 5;          // 0..7
    const int lane = tid & 31;
    const int pos0 = blockIdx.x * PTILE;

    // ---- stage x tile: pos-major gmem reads (coalesced), k-major smem ----
    for (int i = tid; i < PTILE * 32; i += 256) {
        const int pos = i & (PTILE - 1);
        const int cp  = i >> 7;                  // channel pair 0..31
        const float f0 = x[(2 * cp) * N_POS + pos0 + pos];
        const float f1 = x[(2 * cp + 1) * N_POS + pos0 + pos];
        uint16_t h0, l0, h1, l1;
        bf16split(f0, h0, l0);
        bf16split(f1, h1, l1);
        sXhi[pos * CSTR + cp] = pck(h0, h1);
        sXlo[pos * CSTR + cp] = pck(l0, l1);
    }
    __syncthreads();

    const uint32_t bhi_base = smem_u32(sXhi);
    const uint32_t blo_base = smem_u32(sXlo);
    const uint32_t aoff = (uint32_t)((lane & 7) * (CSTR * 4) + (lane >> 3) * 16);
    const int r0c = lane >> 2;
    const int c0  = (lane & 3) << 1;

    for (int t = 0; t < 3; t++) {
        const int sub = wid + t * 8;           // 0..23
        const int h   = sub / 12;              // position half
        const int rr_ = sub % 12;
        const int g   = rr_ >> 2;              // 0=q,1=k,2=v
        const int m0  = (rr_ & 3) << 4;        // row-group base
        const float* wsel = (g == 0) ? wq : (g == 1) ? wk : wv;
        float* dst = (g == 0) ? g_q : (g == 1) ? g_k : g_v;

        // ---- load A fragments (weights) hi+lo, 4 k-steps ----
        uint32_t ah[4][4], al[4][4];
        const int r0 = m0 + r0c;
#pragma unroll
        for (int s = 0; s < 4; s++) {
            const int kb = s << 4;
#pragma unroll
            for (int f = 0; f < 4; f++) {
                const int rr = r0 + ((f & 1) << 3);
                const int cc = kb + c0 + ((f >> 1) << 3);
                const float2 w2 = *(const float2*)&wsel[rr * 64 + cc];
                uint16_t h0, l0, h1, l1;
                bf16split(w2.x, h0, l0);
                bf16split(w2.y, h1, l1);
                ah[s][f] = pck(h0, h1);
                al[s][f] = pck(l0, l1);
            }
        }

        float acc[8][4];
#pragma unroll
        for (int n = 0; n < 8; n++)
#pragma unroll
            for (int j = 0; j < 4; j++) acc[n][j] = 0.f;

#pragma unroll
        for (int n = 0; n < 8; n++) {
            const uint32_t coff = aoff + (uint32_t)((h * 64 + 8 * n) * (CSTR * 4));
            uint32_t bh[8], bl[8];
            LDSM_X4(bh[0], bh[1], bh[2], bh[3], bhi_base + coff);
            LDSM_X4(bh[4], bh[5], bh[6], bh[7], bhi_base + coff + 64);
            LDSM_X4(bl[0], bl[1], bl[2], bl[3], blo_base + coff);
            LDSM_X4(bl[4], bl[5], bl[6], bl[7], blo_base + coff + 64);
#pragma unroll
            for (int s = 0; s < 4; s++) {
                mma_bf16(acc[n], ah[s], bh[2 * s], bh[2 * s + 1]);   // hi*hi
                mma_bf16(acc[n], ah[s], bl[2 * s], bl[2 * s + 1]);   // hi*lo
                mma_bf16(acc[n], al[s], bh[2 * s], bh[2 * s + 1]);   // lo*hi
            }
        }

        // ---- epilogue ----
        const int rowA = m0 + r0c;
        const int colb = pos0 + h * 64 + c0;
#pragma unroll
        for (int n = 0; n < 8; n++) {
            const int cc = colb + 8 * n;
            *(float2*)&dst[rowA * N_POS + cc]       = make_float2(acc[n][0], acc[n][1]);
            *(float2*)&dst[(rowA + 8) * N_POS + cc] = make_float2(acc[n][2], acc[n][3]);
        }
    }
}

// ---------------------------------------------------------------------------
// Kernel B: per-channel 27-tap softmax attention, templated on bias class
// (b is rank-1 in exactly one of kd/kh/kw -> s = fma(q2, k, qb[class]);
// saves the per-tap FADD+FMUL).  4 outputs per thread along W.
// ---------------------------------------------------------------------------
#define TD 4
#define TH 8
#define SD (TD + 2)
#define SH (TH + 2)
#define ROW 68
#define PLANE (SH * ROW)
#define HALO (SD * PLANE)

__device__ __forceinline__ float ex2f(float x) {
    float r;
    asm("ex2.approx.ftz.f32 %0, %1;" : "=f"(r) : "f"(x));
    return r;
}

template<int CLS>
__global__ __launch_bounds__(512) void attn_kernel(
    const float* __restrict__ rel,
    float* __restrict__ out,
    int cbase)
{
    __shared__ __align__(16) float sk[HALO];
    __shared__ __align__(16) float sv[HALO];

    const int c    = cbase + blockIdx.y;
    const int tile = blockIdx.x;
    const int th   = tile & 7;
    const int td   = tile >> 3;
    const int d0 = td * TD, h0 = th * TH;
    const int tid = threadIdx.x;

    // 3 bias values for this channel (class axis only)
    const float b0 = rel[(c - cbase) * 3 + 0];
    const float b1 = rel[(c - cbase) * 3 + 1];
    const float b2 = rel[(c - cbase) * 3 + 2];

    const float* kc = g_k + c * N_POS;
    const float* vc = g_v + c * N_POS;

    for (int i = tid; i < HALO; i += 512) {
        int z   = i / PLANE;
        int r   = i - z * PLANE;
        int y   = r / ROW;
        int col = r - y * ROW;
        int gd = d0 - 1 + z, gh = h0 - 1 + y, gw = col - 1;
        float kvv = 0.f, vvv = 0.f;
        if ((unsigned)gd < 16u && (unsigned)gh < 64u && (unsigned)gw < 64u) {
            int gi = (gd << 12) + (gh << 6) + gw;
            kvv = kc[gi];
            vvv = vc[gi];
        }
        sk[i] = kvv;
        sv[i] = vvv;
    }
    __syncthreads();

    const int lw = tid & 15;
    const int lh = (tid >> 4) & 7;
    const int ld = tid >> 7;

    const int gbase = c * N_POS + ((d0 + ld) << 12) + ((h0 + lh) << 6) + 4 * lw;
    const float4 qv = *(const float4*)(g_q + gbase);

    const float LOG2E = 1.4426950408889634f;
    float q2[4] = {qv.x * LOG2E, qv.y * LOG2E, qv.z * LOG2E, qv.w * LOG2E};
    // qb[t][i] = q2[t] * b_i  (i indexes the class axis)
    float qb[4][3];
#pragma unroll
    for (int t = 0; t < 4; t++) {
        qb[t][0] = q2[t] * b0;
        qb[t][1] = q2[t] * b1;
        qb[t][2] = q2[t] * b2;
    }

    float sp[4] = {0.f, 0.f, 0.f, 0.f};
    float acc[4] = {0.f, 0.f, 0.f, 0.f};

#pragma unroll
    for (int kd = 0; kd < 3; kd++) {
#pragma unroll
        for (int kh = 0; kh < 3; kh++) {
            const int roff = (ld + kd) * PLANE + (lh + kh) * ROW + 4 * lw;
            const float4 ka = *(const float4*)&sk[roff];
            const float2 kb = *(const float2*)&sk[roff + 4];
            const float4 va = *(const float4*)&sv[roff];
            const float2 vb = *(const float2*)&sv[roff + 4];
            float kk[6] = {ka.x, ka.y, ka.z, ka.w, kb.x, kb.y};
            float vv[6] = {va.x, va.y, va.z, va.w, vb.x, vb.y};
#pragma unroll
            for (int kw = 0; kw < 3; kw++) {
                const int ci = (CLS == 0) ? kd : (CLS == 1) ? kh : kw;  // compile-time
#pragma unroll
                for (int t = 0; t < 4; t++) {
                    float p = ex2f(fmaf(q2[t], kk[t + kw], qb[t][ci]));
                    sp[t] += p;
                    acc[t] = fmaf(p, vv[t + kw], acc[t]);
                }
            }
        }
    }

    float4 o4;
    o4.x = __fdividef(acc[0], sp[0]);
    o4.y = __fdividef(acc[1], sp[1]);
    o4.z = __fdividef(acc[2], sp[2]);
    o4.w = __fdividef(acc[3], sp[3]);
    *(float4*)(out + gbase) = o4;
}

// ---------------------------------------------------------------------------
extern "C" void kernel_launch(void* const* d_in, const int* in_sizes, int n_in,
                              void* d_out, int out_size)
{
    const float* x     = (const float*)d_in[0];
    const float* wq    = (const float*)d_in[1];
    const float* wk    = (const float*)d_in[2];
    const float* wv    = (const float*)d_in[3];
    const float* rel_d = (const float*)d_in[4];
    const float* rel_h = (const float*)d_in[5];
    const float* rel_w = (const float*)d_in[6];
    float* out = (float*)d_out;

    qkv_mma_kernel<<<N_POS / PTILE, 256>>>(x, wq, wk, wv);
    attn_kernel<0><<<dim3(32, 21), 512>>>(rel_d, out, 0);
    attn_kernel<1><<<dim3(32, 21), 512>>>(rel_h, out, 21);
    attn_kernel<2><<<dim3(32, 22), 512>>>(rel_w, out, 42);
}

// round 13
// speedup vs baseline: 1.1022x; 1.1022x over previous
#include <cuda_runtime.h>
#include <cuda_bf16.h>
#include <cstdint>

#define N_POS 65536   // 16*64*64

// Scratch (allocation-free rule: __device__ globals)
__device__ float g_q[64 * N_POS];
__device__ float g_k[64 * N_POS];
__device__ float g_v[64 * N_POS];

// ---------------------------------------------------------------------------
// Helpers (arch-agnostic PTX only: mma.sync + ldmatrix, sm_80+)
// ---------------------------------------------------------------------------
__device__ __forceinline__ uint32_t smem_u32(const void* p) {
    return (uint32_t)__cvta_generic_to_shared(p);
}

__device__ __forceinline__ void mma_bf16(float* c, const uint32_t* a, uint32_t b0, uint32_t b1) {
    asm volatile(
        "mma.sync.aligned.m16n8k16.row.col.f32.bf16.bf16.f32 "
        "{%0,%1,%2,%3}, {%4,%5,%6,%7}, {%8,%9}, {%0,%1,%2,%3};"
        : "+f"(c[0]), "+f"(c[1]), "+f"(c[2]), "+f"(c[3])
        : "r"(a[0]), "r"(a[1]), "r"(a[2]), "r"(a[3]), "r"(b0), "r"(b1));
}

#define LDSM_X4(r0, r1, r2, r3, addr)                                          \
    asm volatile("ldmatrix.sync.aligned.m8n8.x4.shared.b16 {%0,%1,%2,%3}, [%4];" \
                 : "=r"(r0), "=r"(r1), "=r"(r2), "=r"(r3) : "r"(addr))

__device__ __forceinline__ void bf16split(float x, uint16_t& h, uint16_t& l) {
    __nv_bfloat16 hb = __float2bfloat16(x);
    __nv_bfloat16 lb = __float2bfloat16(x - __bfloat162float(hb));
    h = __bfloat16_as_ushort(hb);
    l = __bfloat16_as_ushort(lb);
}
__device__ __forceinline__ uint32_t pck(uint16_t lo, uint16_t hi) {
    return (uint32_t)lo | ((uint32_t)hi << 16);
}

// ---------------------------------------------------------------------------
// Kernel A: q/k/v 1x1 conv as bf16 HMMA GEMM with 2-term split
// (hi*hi + hi*lo + lo*hi, fp32 accumulate -> ~1e-5 rel err).
// 256 threads / 8 warps, 2 CTAs per SM (phase overlap across CTAs).
// CTA = 128 positions.  24 warp-subtiles = {q,k,v} x 4 row-groups x 2
// position-halves; each warp walks 3 subtiles sequentially (acc = 32 regs).
// (unchanged from R9 — this restructure cut qkv ~45 -> ~29us)
// ---------------------------------------------------------------------------
#define PTILE 128
#define CSTR 36   // uint32 stride per position column (36*4 = 144 B)

__global__ __launch_bounds__(256, 2) void qkv_mma_kernel(
    const float* __restrict__ x,
    const float* __restrict__ wq,
    const float* __restrict__ wk,
    const float* __restrict__ wv)
{
    __shared__ uint32_t sXhi[PTILE * CSTR];   // 18432 B
    __shared__ uint32_t sXlo[PTILE * CSTR];   // 18432 B

    const int tid  = threadIdx.x;
    const int wid  = tid >> 5;          // 0..7
    const int lane = tid & 31;
    const int pos0 = blockIdx.x * PTILE;

    // ---- stage x tile: pos-major gmem reads (coalesced), k-major smem ----
    for (int i = tid; i < PTILE * 32; i += 256) {
        const int pos = i & (PTILE - 1);
        const int cp  = i >> 7;                  // channel pair 0..31
        const float f0 = x[(2 * cp) * N_POS + pos0 + pos];
        const float f1 = x[(2 * cp + 1) * N_POS + pos0 + pos];
        uint16_t h0, l0, h1, l1;
        bf16split(f0, h0, l0);
        bf16split(f1, h1, l1);
        sXhi[pos * CSTR + cp] = pck(h0, h1);
        sXlo[pos * CSTR + cp] = pck(l0, l1);
    }
    __syncthreads();

    const uint32_t bhi_base = smem_u32(sXhi);
    const uint32_t blo_base = smem_u32(sXlo);
    const uint32_t aoff = (uint32_t)((lane & 7) * (CSTR * 4) + (lane >> 3) * 16);
    const int r0c = lane >> 2;
    const int c0  = (lane & 3) << 1;

    for (int t = 0; t < 3; t++) {
        const int sub = wid + t * 8;           // 0..23
        const int h   = sub / 12;              // position half
        const int rr_ = sub % 12;
        const int g   = rr_ >> 2;              // 0=q,1=k,2=v
        const int m0  = (rr_ & 3) << 4;        // row-group base
        const float* wsel = (g == 0) ? wq : (g == 1) ? wk : wv;
        float* dst = (g == 0) ? g_q : (g == 1) ? g_k : g_v;

        // ---- load A fragments (weights) hi+lo, 4 k-steps ----
        uint32_t ah[4][4], al[4][4];
        const int r0 = m0 + r0c;
#pragma unroll
        for (int s = 0; s < 4; s++) {
            const int kb = s << 4;
#pragma unroll
            for (int f = 0; f < 4; f++) {
                const int rr = r0 + ((f & 1) << 3);
                const int cc = kb + c0 + ((f >> 1) << 3);
                const float2 w2 = *(const float2*)&wsel[rr * 64 + cc];
                uint16_t h0, l0, h1, l1;
                bf16split(w2.x, h0, l0);
                bf16split(w2.y, h1, l1);
                ah[s][f] = pck(h0, h1);
                al[s][f] = pck(l0, l1);
            }
        }

        float acc[8][4];
#pragma unroll
        for (int n = 0; n < 8; n++)
#pragma unroll
            for (int j = 0; j < 4; j++) acc[n][j] = 0.f;

#pragma unroll
        for (int n = 0; n < 8; n++) {
            const uint32_t coff = aoff + (uint32_t)((h * 64 + 8 * n) * (CSTR * 4));
            uint32_t bh[8], bl[8];
            LDSM_X4(bh[0], bh[1], bh[2], bh[3], bhi_base + coff);
            LDSM_X4(bh[4], bh[5], bh[6], bh[7], bhi_base + coff + 64);
            LDSM_X4(bl[0], bl[1], bl[2], bl[3], blo_base + coff);
            LDSM_X4(bl[4], bl[5], bl[6], bl[7], blo_base + coff + 64);
#pragma unroll
            for (int s = 0; s < 4; s++) {
                mma_bf16(acc[n], ah[s], bh[2 * s], bh[2 * s + 1]);   // hi*hi
                mma_bf16(acc[n], ah[s], bl[2 * s], bl[2 * s + 1]);   // hi*lo
                mma_bf16(acc[n], al[s], bh[2 * s], bh[2 * s + 1]);   // lo*hi
            }
        }

        // ---- epilogue ----
        const int rowA = m0 + r0c;
        const int colb = pos0 + h * 64 + c0;
#pragma unroll
        for (int n = 0; n < 8; n++) {
            const int cc = colb + 8 * n;
            *(float2*)&dst[rowA * N_POS + cc]       = make_float2(acc[n][0], acc[n][1]);
            *(float2*)&dst[(rowA + 8) * N_POS + cc] = make_float2(acc[n][2], acc[n][3]);
        }
    }
}

// ---------------------------------------------------------------------------
// Kernel B: per-channel 27-tap softmax attention, single 2048-block launch,
// class specialization via block-uniform dispatch into templated bodies
// (b rank-1 in one of kd/kh/kw -> per-tap s = fma(q2, k, qb[class])).
// 4 outputs per thread along W.
// ---------------------------------------------------------------------------
#define TD 4
#define TH 8
#define SD (TD + 2)
#define SH (TH + 2)
#define ROW 68
#define PLANE (SH * ROW)
#define HALO (SD * PLANE)

__device__ __forceinline__ float ex2f(float x) {
    float r;
    asm("ex2.approx.ftz.f32 %0, %1;" : "=f"(r) : "f"(x));
    return r;
}

template<int CLS>
__device__ __forceinline__ void attn_body(
    float* sk, float* sv,
    const float* __restrict__ rel, int c, int cbase,
    float* __restrict__ out)
{
    const int tile = blockIdx.x;
    const int th   = tile & 7;
    const int td   = tile >> 3;
    const int d0 = td * TD, h0 = th * TH;
    const int tid = threadIdx.x;

    const float b0 = rel[(c - cbase) * 3 + 0];
    const float b1 = rel[(c - cbase) * 3 + 1];
    const float b2 = rel[(c - cbase) * 3 + 2];

    const float* kc = g_k + c * N_POS;
    const float* vc = g_v + c * N_POS;

    for (int i = tid; i < HALO; i += 512) {
        int z   = i / PLANE;
        int r   = i - z * PLANE;
        int y   = r / ROW;
        int col = r - y * ROW;
        int gd = d0 - 1 + z, gh = h0 - 1 + y, gw = col - 1;
        float kvv = 0.f, vvv = 0.f;
        if ((unsigned)gd < 16u && (unsigned)gh < 64u && (unsigned)gw < 64u) {
            int gi = (gd << 12) + (gh << 6) + gw;
            kvv = kc[gi];
            vvv = vc[gi];
        }
        sk[i] = kvv;
        sv[i] = vvv;
    }
    __syncthreads();

    const int lw = tid & 15;
    const int lh = (tid >> 4) & 7;
    const int ld = tid >> 7;

    const int gbase = c * N_POS + ((d0 + ld) << 12) + ((h0 + lh) << 6) + 4 * lw;
    const float4 qv = *(const float4*)(g_q + gbase);

    const float LOG2E = 1.4426950408889634f;
    float q2[4] = {qv.x * LOG2E, qv.y * LOG2E, qv.z * LOG2E, qv.w * LOG2E};
    float qb[4][3];
#pragma unroll
    for (int t = 0; t < 4; t++) {
        qb[t][0] = q2[t] * b0;
        qb[t][1] = q2[t] * b1;
        qb[t][2] = q2[t] * b2;
    }

    float sp[4] = {0.f, 0.f, 0.f, 0.f};
    float acc[4] = {0.f, 0.f, 0.f, 0.f};

#pragma unroll
    for (int kd = 0; kd < 3; kd++) {
#pragma unroll
        for (int kh = 0; kh < 3; kh++) {
            const int roff = (ld + kd) * PLANE + (lh + kh) * ROW + 4 * lw;
            const float4 ka = *(const float4*)&sk[roff];
            const float2 kb = *(const float2*)&sk[roff + 4];
            const float4 va = *(const float4*)&sv[roff];
            const float2 vb = *(const float2*)&sv[roff + 4];
            float kk[6] = {ka.x, ka.y, ka.z, ka.w, kb.x, kb.y};
            float vv[6] = {va.x, va.y, va.z, va.w, vb.x, vb.y};
#pragma unroll
            for (int kw = 0; kw < 3; kw++) {
                const int ci = (CLS == 0) ? kd : (CLS == 1) ? kh : kw;  // compile-time
#pragma unroll
                for (int t = 0; t < 4; t++) {
                    float p = ex2f(fmaf(q2[t], kk[t + kw], qb[t][ci]));
                    sp[t] += p;
                    acc[t] = fmaf(p, vv[t + kw], acc[t]);
                }
            }
        }
    }

    float4 o4;
    o4.x = __fdividef(acc[0], sp[0]);
    o4.y = __fdividef(acc[1], sp[1]);
    o4.z = __fdividef(acc[2], sp[2]);
    o4.w = __fdividef(acc[3], sp[3]);
    *(float4*)(out + gbase) = o4;
}

__global__ __launch_bounds__(512) void attn_kernel(
    const float* __restrict__ rel_d,
    const float* __restrict__ rel_h,
    const float* __restrict__ rel_w,
    float* __restrict__ out)
{
    __shared__ __align__(16) float sk[HALO];
    __shared__ __align__(16) float sv[HALO];

    const int c = blockIdx.y;
    if (c < 21)      attn_body<0>(sk, sv, rel_d, c, 0,  out);
    else if (c < 42) attn_body<1>(sk, sv, rel_h, c, 21, out);
    else             attn_body<2>(sk, sv, rel_w, c, 42, out);
}

// ---------------------------------------------------------------------------
extern "C" void kernel_launch(void* const* d_in, const int* in_sizes, int n_in,
                              void* d_out, int out_size)
{
    const float* x     = (const float*)d_in[0];
    const float* wq    = (const float*)d_in[1];
    const float* wk    = (const float*)d_in[2];
    const float* wv    = (const float*)d_in[3];
    const float* rel_d = (const float*)d_in[4];
    const float* rel_h = (const float*)d_in[5];
    const float* rel_w = (const float*)d_in[6];
    float* out = (float*)d_out;

    qkv_mma_kernel<<<N_POS / PTILE, 256>>>(x, wq, wk, wv);
    attn_kernel<<<dim3(32, 64), 512>>>(rel_d, rel_h, rel_w, out);
}